// round 10
// baseline (speedup 1.0000x reference)
#include <cuda_runtime.h>
#include <cstdint>

// Problem constants (fixed by reference setup_inputs)
#define NS    16
#define NP    2048
#define DIM   64
#define KNN   16
#define BLOCK 128
#define QB    256              // queries per CTA (2 per thread)
#define HALF  2                // DB split factor
#define CAND  (NP / HALF)      // 1024 candidates per CTA
#define TILE  128              // candidates per smem tile
#define ROWF  68               // padded floats per smem row (272 B)
#define ROWB  (ROWF * 4)
#define NTOT  (NS * NP * KNN)  // 524288
#define HSTR  136              // heap stride in bytes (17 * 8 -> 2-way conflicts max)

// dynamic smem layout
#define SM_TILE_B  (TILE * ROWF * 4)          // 34816
#define SM_SX2_B   (TILE * 4)                 //   512
#define SM_HEAP_B  (QB * HSTR)                // 34816
#define SM_TOTAL   (SM_TILE_B + SM_SX2_B + SM_HEAP_B)   // 70144

typedef unsigned long long ull;
#define INFKEY 0x7f800000ffffffffULL   // +inf dist bits, max idx

// Partial sorted top-K keys (static device scratch — no allocation)
__device__ ull g_pk[HALF][NS * NP][KNN];

// ---- packed f32x2 helpers (sm_103a) ------------------------------------
__device__ __forceinline__ ull pk2(float x, float y) {
    ull r; asm("mov.b64 %0, {%1, %2};" : "=l"(r) : "f"(x), "f"(y)); return r;
}
__device__ __forceinline__ void unpk2(float& lo, float& hi, ull v) {
    asm("mov.b64 {%0, %1}, %2;" : "=f"(lo), "=f"(hi) : "l"(v));
}
__device__ __forceinline__ ull fma2(ull a, ull b, ull c) {
    ull d; asm("fma.rn.f32x2 %0, %1, %2, %3;" : "=l"(d) : "l"(a), "l"(b), "l"(c)); return d;
}
__device__ __forceinline__ ull add2(ull a, ull b) {
    ull d; asm("add.rn.f32x2 %0, %1, %2;" : "=l"(d) : "l"(a), "l"(b)); return d;
}
__device__ __forceinline__ void lds2x64(ull& a, ull& b, unsigned addr) {
    asm volatile("ld.shared.v2.b64 {%0, %1}, [%2];" : "=l"(a), "=l"(b) : "r"(addr));
}

// Replace root of a 16-element max-heap with a smaller key; sift down.
// Returns the new root key (current max of the 16 kept candidates).
__device__ __forceinline__ ull heap_replace(ull* hp, ull key) {
    ull newroot = key;
    int pos = 0;
#pragma unroll
    for (int lvl = 0; lvl < 4; ++lvl) {
        int c = 2 * pos + 1;
        if (c > 15) break;
        ull ck = hp[c];
        if (c + 1 < 16) { ull c2 = hp[c + 1]; if (c2 > ck) { ck = c2; c++; } }
        if (key >= ck) break;
        hp[pos] = ck;
        if (lvl == 0) newroot = ck;
        pos = c;
    }
    hp[pos] = key;
    return newroot;
}

// In-place heapsort of the 16-key max-heap -> ascending order in hp[0..15].
__device__ __forceinline__ void heap_sort16(ull* hp) {
    for (int end = 15; end > 0; --end) {
        ull mx = hp[0];
        ull last = hp[end];
        hp[end] = mx;
        int pos = 0;
        while (true) {
            int c = 2 * pos + 1;
            if (c >= end) break;
            ull ck = hp[c];
            if (c + 1 < end) { ull c2 = hp[c + 1]; if (c2 > ck) { ck = c2; c++; } }
            if (last >= ck) break;
            hp[pos] = ck;
            pos = c;
        }
        hp[pos] = last;
    }
}

__global__ void __launch_bounds__(BLOCK, 2)
knn_part_kernel(const float* __restrict__ h) {
    extern __shared__ __align__(16) char dsm[];
    float* smem  = (float*)dsm;                           // padded db tile
    float* sx2   = (float*)(dsm + SM_TILE_B);             // db squared norms
    char*  heaps = dsm + SM_TILE_B + SM_SX2_B;            // per-query heaps

    const int bx   = blockIdx.x;
    const int half = bx & 1;
    const int t2   = bx >> 1;
    const int b    = t2 >> 3;            // NP/QB = 8 query blocks per sample
    const int qblk = (t2 & 7) * QB;
    const int tid  = threadIdx.x;
    const float* hb = h + (size_t)b * NP * DIM;

    const int q0 = qblk + tid;
    const int q1 = qblk + BLOCK + tid;

    ull* hp0 = (ull*)(heaps + (size_t)tid * HSTR);
    ull* hp1 = (ull*)(heaps + (size_t)(BLOCK + tid) * HSTR);
#pragma unroll
    for (int k = 0; k < KNN; k++) { hp0[k] = INFKEY; hp1[k] = INFKEY; }
    ull root0 = INFKEY, root1 = INFKEY;

    // ---- two register-resident packed query vectors + squared norms ----
    ull q0p[DIM / 2], q1p[DIM / 2];
    float x2q0 = 0.0f, x2q1 = 0.0f;
    {
        const float4* g0 = (const float4*)(hb + (size_t)q0 * DIM);
        const float4* g1 = (const float4*)(hb + (size_t)q1 * DIM);
#pragma unroll
        for (int i = 0; i < DIM / 4; i++) {
            float4 v = g0[i];
            x2q0 = fmaf(v.x, v.x, x2q0); x2q0 = fmaf(v.y, v.y, x2q0);
            x2q0 = fmaf(v.z, v.z, x2q0); x2q0 = fmaf(v.w, v.w, x2q0);
            q0p[2 * i] = pk2(v.x, v.y);  q0p[2 * i + 1] = pk2(v.z, v.w);
            float4 w = g1[i];
            x2q1 = fmaf(w.x, w.x, x2q1); x2q1 = fmaf(w.y, w.y, x2q1);
            x2q1 = fmaf(w.z, w.z, x2q1); x2q1 = fmaf(w.w, w.w, x2q1);
            q1p[2 * i] = pk2(w.x, w.y);  q1p[2 * i + 1] = pk2(w.z, w.w);
        }
    }

    const unsigned sbase = (unsigned)__cvta_generic_to_shared(smem);
    const int gbase = half * CAND;

    for (int tt = 0; tt < CAND / TILE; tt++) {
        __syncthreads();  // previous tile fully consumed
        {   // cooperative coalesced tile load with row padding
            const float4* gt = (const float4*)(hb + (size_t)(gbase + tt * TILE) * DIM);
#pragma unroll
            for (int i = 0; i < (TILE * DIM / 4) / BLOCK; i++) {  // 16 iters
                int idx = i * BLOCK + tid;
                int row = idx >> 4;
                int col = idx & 15;
                ((float4*)smem)[row * (ROWF / 4) + col] = gt[idx];
            }
        }
        __syncthreads();
        {   // per-row squared norm (one row per thread; TILE == BLOCK)
            const float4* rp = (const float4*)(smem + tid * ROWF);
            float s = 0.0f;
#pragma unroll
            for (int i = 0; i < DIM / 4; i++) {
                float4 v = rp[i];
                s = fmaf(v.x, v.x, s); s = fmaf(v.y, v.y, s);
                s = fmaf(v.z, v.z, s); s = fmaf(v.w, v.w, s);
            }
            sx2[tid] = s;
        }
        __syncthreads();

        unsigned rb = sbase;
        for (int j = 0; j < TILE; j++, rb += ROWB) {
            ull a00 = 0ull, a01 = 0ull, a10 = 0ull, a11 = 0ull;
#pragma unroll
            for (int i = 0; i < 16; i += 2) {     // 16 chunks of 16 B
                ull v0, v1, v2, v3;
                lds2x64(v0, v1, rb + i * 16);
                lds2x64(v2, v3, rb + i * 16 + 16);
                a00 = fma2(q0p[2 * i],     v0, a00);
                a01 = fma2(q0p[2 * i + 1], v1, a01);
                a10 = fma2(q1p[2 * i],     v0, a10);
                a11 = fma2(q1p[2 * i + 1], v1, a11);
                a00 = fma2(q0p[2 * i + 2], v2, a00);
                a01 = fma2(q0p[2 * i + 3], v3, a01);
                a10 = fma2(q1p[2 * i + 2], v2, a10);
                a11 = fma2(q1p[2 * i + 3], v3, a11);
            }
            float l0, h0; unpk2(l0, h0, add2(a00, a01));
            float l1, h1; unpk2(l1, h1, add2(a10, a11));
            const float sj = sx2[j];
            const float d0 = fmaf(-2.0f, l0 + h0, x2q0 + sj);
            const float d1 = fmaf(-2.0f, l1 + h1, x2q1 + sj);
            const unsigned gidx = (unsigned)(gbase + tt * TILE + j);

            // composite key: (clamped dist bits, global-in-sample index).
            // Lexicographic order == top_k's value-then-lowest-index order.
            const ull k0 = ((ull)__float_as_uint(fmaxf(d0, 0.0f)) << 32) | gidx;
            const ull k1 = ((ull)__float_as_uint(fmaxf(d1, 0.0f)) << 32) | gidx;
            if (k0 < root0) root0 = heap_replace(hp0, k0);
            if (k1 < root1) root1 = heap_replace(hp1, k1);
        }
    }

    // sort each heap ascending and dump partial results
    heap_sort16(hp0);
    heap_sort16(hp1);
    const size_t r0 = (size_t)b * NP + q0;
    const size_t r1 = (size_t)b * NP + q1;
#pragma unroll
    for (int k = 0; k < KNN; k++) {
        g_pk[half][r0][k] = hp0[k];
        g_pk[half][r1][k] = hp1[k];
    }
}

// Merge the two sorted 16-key lists per query; keys are unique (contain idx),
// and lexicographic order preserves top_k tie semantics.
__global__ void __launch_bounds__(BLOCK, 8)
knn_merge_kernel(float* __restrict__ out, int write_edges) {
    const int gq = blockIdx.x * BLOCK + threadIdx.x;   // 0..NS*NP-1
    const int b  = gq >> 11;                           // / NP
    const int off = b * NP;
    const size_t o = (size_t)gq * KNN;

    int i = 0, j = 0;
#pragma unroll
    for (int k = 0; k < KNN; k++) {    // i+j=k<=15 so no bounds checks needed
        ull k0 = g_pk[0][gq][i], k1 = g_pk[1][gq][j];
        bool take0 = k0 < k1;
        ull kv = take0 ? k0 : k1;
        i += take0; j += !take0;
        out[o + k] = __uint_as_float((unsigned)(kv >> 32));
        if (write_edges) {
            out[(size_t)NTOT + o + k]     = (float)((int)(kv & 0xffffffffu) + off);
            out[(size_t)2 * NTOT + o + k] = (float)gq;        // src = q + b*NP
        }
    }
}

extern "C" void kernel_launch(void* const* d_in, const int* in_sizes, int n_in,
                              void* d_out, int out_size) {
    const float* h = (const float*)d_in[0];
    int write_edges = (out_size >= 3 * NTOT) ? 1 : 0;
    cudaFuncSetAttribute(knn_part_kernel,
                         cudaFuncAttributeMaxDynamicSharedMemorySize, SM_TOTAL);
    knn_part_kernel<<<NS * (NP / QB) * HALF, BLOCK, SM_TOTAL>>>(h);
    knn_merge_kernel<<<NS * NP / BLOCK, BLOCK>>>((float*)d_out, write_edges);
}

// round 12
// speedup vs baseline: 1.5075x; 1.5075x over previous
#include <cuda_runtime.h>
#include <cstdint>

// Problem constants (fixed by reference setup_inputs)
#define NS    16
#define NP    2048
#define DIM   64
#define KNN   16
#define BLOCK 128
#define QB    256              // queries per CTA (2 per thread)
#define HALF  2                // DB split factor
#define CAND  (NP / HALF)      // 1024 candidates per CTA
#define TILE  128              // candidates per smem tile
#define ROWF  68               // padded floats per smem row (272 B)
#define ROWB  (ROWF * 4)
#define NTOT  (NS * NP * KNN)  // 524288
#define BUFS  8                // ring-buffer slots per query per thread

typedef unsigned long long ull;

// Partial top-K scratch (static device arrays — no allocation)
__device__ float g_pd[HALF][NS * NP][KNN];
__device__ int   g_pi[HALF][NS * NP][KNN];

// ---- packed f32x2 helpers (sm_103a) ------------------------------------
__device__ __forceinline__ ull pk2(float x, float y) {
    ull r; asm("mov.b64 %0, {%1, %2};" : "=l"(r) : "f"(x), "f"(y)); return r;
}
__device__ __forceinline__ void unpk2(float& lo, float& hi, ull v) {
    asm("mov.b64 {%0, %1}, %2;" : "=f"(lo), "=f"(hi) : "l"(v));
}
__device__ __forceinline__ ull fma2(ull a, ull b, ull c) {
    ull d; asm("fma.rn.f32x2 %0, %1, %2, %3;" : "=l"(d) : "l"(a), "l"(b), "l"(c)); return d;
}
__device__ __forceinline__ ull add2(ull a, ull b) {
    ull d; asm("add.rn.f32x2 %0, %1, %2;" : "=l"(d) : "l"(a), "l"(b)); return d;
}
__device__ __forceinline__ void lds2x64(ull& a, ull& b, unsigned addr) {
    asm volatile("ld.shared.v2.b64 {%0, %1}, [%2];" : "=l"(a), "=l"(b) : "r"(addr));
}

// Branchless sorted insert into ascending 16-list (strict < keeps stream order
// on ties -> matches top_k lowest-index-first tie-breaking).
__device__ __forceinline__ void insert16(float (&bd)[KNN], int (&bi)[KNN],
                                         float d, int ix) {
    bool pk = d < bd[KNN - 1];
#pragma unroll
    for (int k = KNN - 1; k >= 1; --k) {
        bool pk1 = d < bd[k - 1];
        bd[k] = pk ? (pk1 ? bd[k - 1] : d)  : bd[k];
        bi[k] = pk ? (pk1 ? bi[k - 1] : ix) : bi[k];
        pk = pk1;
    }
    if (pk) { bd[0] = d; bi[0] = ix; }
}

// Flush buffered candidates. Items buffered under a stale (looser) threshold
// are skipped with 1 compare instead of a full insert — the threshold bd[15]
// tightens as earlier items in the same batch are inserted.
__device__ __forceinline__ void flushbuf(float (&bd)[KNN], int (&bi)[KNN],
                                         unsigned bufaddr, int& cnt) {
    for (int u = 0; u < cnt; ++u) {
        float fd; int fi;
        asm volatile("ld.shared.v2.b32 {%0, %1}, [%2];"
                     : "=f"(fd), "=r"(fi)
                     : "r"(bufaddr + (unsigned)(u * BLOCK * 8)));
        if (fd < bd[KNN - 1]) insert16(bd, bi, fd, fi);   // stale-skip
    }
    cnt = 0;
}

__global__ void __launch_bounds__(BLOCK, 2)
knn_part_kernel(const float* __restrict__ h) {
    __shared__ __align__(16) float smem[TILE * ROWF];    // 34816 B
    __shared__ float sx2[TILE];                          //   512 B
    __shared__ __align__(16) ull sbuf[2 * BUFS * BLOCK]; // 16384 B (51.7 KB total)

    const int bx   = blockIdx.x;
    const int half = bx & 1;
    const int t2   = bx >> 1;
    const int b    = t2 >> 3;            // NP/QB = 8 query blocks per sample
    const int qblk = (t2 & 7) * QB;
    const int tid  = threadIdx.x;
    const float* hb = h + (size_t)b * NP * DIM;

    const int q0 = qblk + tid;
    const int q1 = qblk + BLOCK + tid;

    // ---- two register-resident packed query vectors + squared norms ----
    ull q0p[DIM / 2], q1p[DIM / 2];
    float x2q0 = 0.0f, x2q1 = 0.0f;
    {
        const float4* g0 = (const float4*)(hb + (size_t)q0 * DIM);
        const float4* g1 = (const float4*)(hb + (size_t)q1 * DIM);
#pragma unroll
        for (int i = 0; i < DIM / 4; i++) {
            float4 v = g0[i];
            x2q0 = fmaf(v.x, v.x, x2q0); x2q0 = fmaf(v.y, v.y, x2q0);
            x2q0 = fmaf(v.z, v.z, x2q0); x2q0 = fmaf(v.w, v.w, x2q0);
            q0p[2 * i] = pk2(v.x, v.y);  q0p[2 * i + 1] = pk2(v.z, v.w);
            float4 w = g1[i];
            x2q1 = fmaf(w.x, w.x, x2q1); x2q1 = fmaf(w.y, w.y, x2q1);
            x2q1 = fmaf(w.z, w.z, x2q1); x2q1 = fmaf(w.w, w.w, x2q1);
            q1p[2 * i] = pk2(w.x, w.y);  q1p[2 * i + 1] = pk2(w.z, w.w);
        }
    }

    float bd0[KNN], bd1[KNN];
    int   bi0[KNN], bi1[KNN];
#pragma unroll
    for (int k = 0; k < KNN; k++) {
        bd0[k] = __int_as_float(0x7f800000); bi0[k] = 0;
        bd1[k] = __int_as_float(0x7f800000); bi1[k] = 0;
    }
    int cnt0 = 0, cnt1 = 0;

    const unsigned sbase = (unsigned)__cvta_generic_to_shared(smem);
    const unsigned bufb  = (unsigned)__cvta_generic_to_shared(sbuf) + tid * 8;
    const unsigned buf0  = bufb;
    const unsigned buf1  = bufb + BUFS * BLOCK * 8;

    const int gbase = half * CAND;

    for (int tt = 0; tt < CAND / TILE; tt++) {
        __syncthreads();  // previous tile fully consumed
        {   // cooperative coalesced tile load with row padding
            const float4* gt = (const float4*)(hb + (size_t)(gbase + tt * TILE) * DIM);
#pragma unroll
            for (int i = 0; i < (TILE * DIM / 4) / BLOCK; i++) {  // 16 iters
                int idx = i * BLOCK + tid;
                int row = idx >> 4;
                int col = idx & 15;
                ((float4*)smem)[row * (ROWF / 4) + col] = gt[idx];
            }
        }
        __syncthreads();
        {   // per-row squared norm (one row per thread; TILE == BLOCK)
            const float4* rp = (const float4*)(smem + tid * ROWF);
            float s = 0.0f;
#pragma unroll
            for (int i = 0; i < DIM / 4; i++) {
                float4 v = rp[i];
                s = fmaf(v.x, v.x, s); s = fmaf(v.y, v.y, s);
                s = fmaf(v.z, v.z, s); s = fmaf(v.w, v.w, s);
            }
            sx2[tid] = s;
        }
        __syncthreads();

        unsigned rb = sbase;
        for (int j = 0; j < TILE; j++, rb += ROWB) {
            ull a00 = 0ull, a01 = 0ull, a10 = 0ull, a11 = 0ull;
#pragma unroll
            for (int i = 0; i < 16; i += 2) {     // 16 chunks of 16 B
                ull v0, v1, v2, v3;
                lds2x64(v0, v1, rb + i * 16);
                lds2x64(v2, v3, rb + i * 16 + 16);
                a00 = fma2(q0p[2 * i],     v0, a00);
                a01 = fma2(q0p[2 * i + 1], v1, a01);
                a10 = fma2(q1p[2 * i],     v0, a10);
                a11 = fma2(q1p[2 * i + 1], v1, a11);
                a00 = fma2(q0p[2 * i + 2], v2, a00);
                a01 = fma2(q0p[2 * i + 3], v3, a01);
                a10 = fma2(q1p[2 * i + 2], v2, a10);
                a11 = fma2(q1p[2 * i + 3], v3, a11);
            }
            float l0, h0; unpk2(l0, h0, add2(a00, a01));
            float l1, h1; unpk2(l1, h1, add2(a10, a11));
            const float sj = sx2[j];
            const float d0 = fmaf(-2.0f, l0 + h0, x2q0 + sj);
            const float d1 = fmaf(-2.0f, l1 + h1, x2q1 + sj);
            const int gidx = gbase + tt * TILE + j;

            if (d0 < bd0[KNN - 1]) {   // predicated push into ring buffer
                asm volatile("st.shared.v2.b32 [%0], {%1, %2};"
                             :: "r"(buf0 + (unsigned)(cnt0 * (BLOCK * 8))),
                                "f"(d0), "r"(gidx) : "memory");
                cnt0++;
            }
            if (d1 < bd1[KNN - 1]) {
                asm volatile("st.shared.v2.b32 [%0], {%1, %2};"
                             :: "r"(buf1 + (unsigned)(cnt1 * (BLOCK * 8))),
                                "f"(d1), "r"(gidx) : "memory");
                cnt1++;
            }
            // (cnt0|cnt1) has bit3 set iff either counter reached BUFS=8
            if (__ballot_sync(0xffffffffu, (cnt0 | cnt1) >= BUFS)) {
                flushbuf(bd0, bi0, buf0, cnt0);
                flushbuf(bd1, bi1, buf1, cnt1);
            }
        }
    }
    flushbuf(bd0, bi0, buf0, cnt0);
    flushbuf(bd1, bi1, buf1, cnt1);

    const size_t r0 = (size_t)b * NP + q0;
    const size_t r1 = (size_t)b * NP + q1;
#pragma unroll
    for (int k = 0; k < KNN; k++) {
        g_pd[half][r0][k] = bd0[k];  g_pi[half][r0][k] = bi0[k];
        g_pd[half][r1][k] = bd1[k];  g_pi[half][r1][k] = bi1[k];
    }
}

// Merge the two half-DB sorted-16 lists. Half-0 candidate indices are all
// smaller than half-1's, so <= favors half 0 = lowest-index-first on ties.
__global__ void __launch_bounds__(BLOCK, 8)
knn_merge_kernel(float* __restrict__ out, int write_edges) {
    const int gq = blockIdx.x * BLOCK + threadIdx.x;   // 0..NS*NP-1
    const int b  = gq >> 11;                           // / NP
    const int off = b * NP;
    const size_t o = (size_t)gq * KNN;

    int i = 0, j = 0;
#pragma unroll
    for (int k = 0; k < KNN; k++) {    // i+j=k<=15 so no bounds checks needed
        float d0 = g_pd[0][gq][i], d1 = g_pd[1][gq][j];
        bool take0 = d0 <= d1;
        float dv = take0 ? d0 : d1;
        int   ix = take0 ? g_pi[0][gq][i] : g_pi[1][gq][j];
        i += take0; j += !take0;
        out[o + k] = dv;
        if (write_edges) {
            out[(size_t)NTOT + o + k]     = (float)(ix + off);
            out[(size_t)2 * NTOT + o + k] = (float)gq;        // src = q + b*NP
        }
    }
}

extern "C" void kernel_launch(void* const* d_in, const int* in_sizes, int n_in,
                              void* d_out, int out_size) {
    const float* h = (const float*)d_in[0];
    int write_edges = (out_size >= 3 * NTOT) ? 1 : 0;
    knn_part_kernel<<<NS * (NP / QB) * HALF, BLOCK>>>(h);
    knn_merge_kernel<<<NS * NP / BLOCK, BLOCK>>>((float*)d_out, write_edges);
}